// round 7
// baseline (speedup 1.0000x reference)
#include <cuda_runtime.h>
#include <cuda_bf16.h>
#include <mma.h>

using namespace nvcuda;

#define NB    2048
#define NPH   10
#define NN    (NB*NPH)      // 20480
#define HD    128
#define NHEADS 4
#define NL    2
#define CDIM  32
#define FDIM  128
#define PCOLS 1536
// packed column offsets:
//   [0,512)      GAT xl
//   [512,1024)   GAT xr
//   [1024,1152)  CG fs
//   [1152,1280)  CG ss
//   [1280,1408)  CG fd
//   [1408,1536)  CG sd

// ---------------------------------------------------------------------------
// Scratch
// ---------------------------------------------------------------------------
__device__ float g_X [2*NN*HD];
__device__ float g_NX[2*NN*HD];
__device__ float g_PM[NN*PCOLS];
__device__ float g_PO[NN*PCOLS];
__device__ float g_WPM[NL*HD*PCOLS];   // tf32-rounded
__device__ float g_WPO[NL*HD*PCOLS];   // tf32-rounded
__device__ float g_WN [NL*HD*HD];      // tf32-rounded node weights

// ---------------------------------------------------------------------------
// cp.async helpers
// ---------------------------------------------------------------------------
__device__ __forceinline__ void cp_async16(void* smem_dst, const void* gmem_src) {
    unsigned saddr = (unsigned)__cvta_generic_to_shared(smem_dst);
    asm volatile("cp.async.ca.shared.global [%0], [%1], 16;\n" :: "r"(saddr), "l"(gmem_src));
}
__device__ __forceinline__ void cp_commit() {
    asm volatile("cp.async.commit_group;\n");
}
template<int N> __device__ __forceinline__ void cp_wait() {
    asm volatile("cp.async.wait_group %0;\n" :: "n"(N));
}

// ---------------------------------------------------------------------------
// Weight packing (weights pre-rounded to tf32: bit-identical to per-use RN)
// ---------------------------------------------------------------------------
__global__ void pack_kernel(const float* __restrict__ gbWl, const float* __restrict__ gbWr,
                            const float* __restrict__ grWl, const float* __restrict__ grWr,
                            const float* __restrict__ clWf, const float* __restrict__ clWs,
                            const float* __restrict__ crWf, const float* __restrict__ crWs)
{
    int idx = blockIdx.x * blockDim.x + threadIdx.x;
    const int total = NL * HD * PCOLS;
    if (idx >= total) return;
    int l   = idx / (HD * PCOLS);
    int rem = idx - l * (HD * PCOLS);
    int k   = rem / PCOLS;
    int col = rem - k * PCOLS;
    float vm, vo;
    if (col < 512) {
        vm = gbWl[(l*HD + k)*512 + col];
        vo = grWl[(l*HD + k)*512 + col];
    } else if (col < 1024) {
        int c = col - 512;
        vm = grWr[(l*HD + k)*512 + c];
        vo = gbWr[(l*HD + k)*512 + c];
    } else if (col < 1152) {
        int c = col - 1024;
        vm = clWf[(l*2*HD + HD + k)*HD + c];
        vo = crWf[(l*2*HD + HD + k)*HD + c];
    } else if (col < 1280) {
        int c = col - 1152;
        vm = clWs[(l*2*HD + HD + k)*HD + c];
        vo = crWs[(l*2*HD + HD + k)*HD + c];
    } else if (col < 1408) {
        int c = col - 1280;
        vm = crWf[(l*2*HD + k)*HD + c];
        vo = clWf[(l*2*HD + k)*HD + c];
    } else {
        int c = col - 1408;
        vm = crWs[(l*2*HD + k)*HD + c];
        vo = clWs[(l*2*HD + k)*HD + c];
    }
    g_WPM[idx] = wmma::__float_to_tf32(vm);
    g_WPO[idx] = wmma::__float_to_tf32(vo);
}

__global__ void pack_node_kernel(const float* __restrict__ nodeW)
{
    int idx = blockIdx.x * blockDim.x + threadIdx.x;
    if (idx >= NL*HD*HD) return;
    g_WN[idx] = wmma::__float_to_tf32(nodeW[idx]);
}

// ---------------------------------------------------------------------------
// Encoder
// ---------------------------------------------------------------------------
__global__ void encoder_kernel(const float* __restrict__ x_my, const float* __restrict__ x_opp,
                               const float* __restrict__ W, const float* __restrict__ b,
                               float* __restrict__ X)
{
    int idx = blockIdx.x * blockDim.x + threadIdx.x;
    if (idx >= 2*NN*HD) return;
    int row = idx >> 7, c = idx & 127;
    const float* x = (row < NN) ? (x_my + (size_t)row*CDIM) : (x_opp + (size_t)(row-NN)*CDIM);
    float acc = b[c];
#pragma unroll
    for (int k = 0; k < CDIM; k++) acc += x[k] * W[k*HD + c];
    X[idx] = acc;
}

// ---------------------------------------------------------------------------
// tf32 tensor-core GEMM. 8 warps (4m x 2n), block 128x128, warp tile 32x64,
// BK=32, cp.async double-buffered. B (weights) pre-rounded: A converts only.
// ---------------------------------------------------------------------------
#define AS_STRIDE 36
#define BS_STRIDE 132
#define AS_STAGE  (128*AS_STRIDE)
#define BS_STAGE  (32*BS_STRIDE)
#define GEMM_SMEM ((2*AS_STAGE + 2*BS_STAGE)*4)  // 70656 B

__global__ __launch_bounds__(256, 2) void tc_gemm(
    const float* __restrict__ A0, const float* __restrict__ A1,
    const float* __restrict__ W0, const float* __restrict__ W1,
    const float* __restrict__ bias,
    float* __restrict__ C0, float* __restrict__ C1,
    int M, int Nc, int K)
{
    const float* A = blockIdx.z ? A1 : A0;
    const float* W = blockIdx.z ? W1 : W0;
    float* C       = blockIdx.z ? C1 : C0;

    extern __shared__ float smem[];
    float* As = smem;                  // [2][128][36]
    float* Bs = smem + 2*AS_STAGE;     // [2][32][132]

    const int tid = threadIdx.x;
    const int bm = blockIdx.y * 128;
    const int bn = blockIdx.x * 128;
    const int warp = tid >> 5;
    const int wm = warp & 3;           // 32-row slab
    const int wn = warp >> 2;          // 64-col slab

    wmma::fragment<wmma::accumulator, 16, 16, 8, float> acc[2][4];

    if (bias) {
        for (int i = tid; i < 16*128; i += 256)
            As[(i >> 7)*128 + (i & 127)] = bias[bn + (i & 127)];
        __syncthreads();
#pragma unroll
        for (int mi = 0; mi < 2; mi++)
#pragma unroll
            for (int ni = 0; ni < 4; ni++)
                wmma::load_matrix_sync(acc[mi][ni], &As[wn*64 + ni*16], 128,
                                       wmma::mem_row_major);
        __syncthreads();
    } else {
#pragma unroll
        for (int mi = 0; mi < 2; mi++)
#pragma unroll
            for (int ni = 0; ni < 4; ni++)
                wmma::fill_fragment(acc[mi][ni], 0.f);
    }

    const int ar = tid >> 3, ac = (tid & 7) * 4;    // A: 32 rows/iter, 8 f4 per row
    const int br = tid >> 5, bc = (tid & 31) * 4;   // B: 8 rows/iter, 32 f4 per row

    auto load_stage = [&](int kt, int buf) {
        float* as = As + buf*AS_STAGE;
        float* bs = Bs + buf*BS_STAGE;
#pragma unroll
        for (int it = 0; it < 4; ++it) {
            int r  = ar + it*32;
            cp_async16(&as[r*AS_STRIDE + ac], A + (size_t)(bm + r)*K + kt + ac);
            int r2 = br + it*8;
            cp_async16(&bs[r2*BS_STRIDE + bc], W + (size_t)(kt + r2)*Nc + bn + bc);
        }
        cp_commit();
    };

    const int T = K >> 5;
    load_stage(0, 0);

    for (int t = 0; t < T; t++) {
        if (t + 1 < T) load_stage((t+1) << 5, (t+1) & 1);
        if (t + 1 < T) cp_wait<1>(); else cp_wait<0>();
        __syncthreads();

        const float* as = As + (t & 1)*AS_STAGE;
        const float* bs = Bs + (t & 1)*BS_STAGE;
#pragma unroll
        for (int ks = 0; ks < 32; ks += 8) {
            wmma::fragment<wmma::matrix_a, 16, 16, 8, wmma::precision::tf32,
                           wmma::row_major> a0, a1;
            wmma::load_matrix_sync(a0, &as[(wm*32)*AS_STRIDE + ks], AS_STRIDE);
            wmma::load_matrix_sync(a1, &as[(wm*32 + 16)*AS_STRIDE + ks], AS_STRIDE);
#pragma unroll
            for (int e = 0; e < a0.num_elements; e++) {
                a0.x[e] = wmma::__float_to_tf32(a0.x[e]);
                a1.x[e] = wmma::__float_to_tf32(a1.x[e]);
            }
#pragma unroll
            for (int ni = 0; ni < 4; ni++) {
                wmma::fragment<wmma::matrix_b, 16, 16, 8, wmma::precision::tf32,
                               wmma::row_major> b;
                wmma::load_matrix_sync(b, &bs[ks*BS_STRIDE + wn*64 + ni*16], BS_STRIDE);
                wmma::mma_sync(acc[0][ni], a0, b, acc[0][ni]);
                wmma::mma_sync(acc[1][ni], a1, b, acc[1][ni]);
            }
        }
        __syncthreads();
    }

#pragma unroll
    for (int mi = 0; mi < 2; mi++)
#pragma unroll
        for (int ni = 0; ni < 4; ni++)
            wmma::store_matrix_sync(
                C + (size_t)(bm + wm*32 + mi*16)*Nc + bn + wn*64 + ni*16,
                acc[mi][ni], Nc, wmma::mem_row_major);
}

// ---------------------------------------------------------------------------
// Fused per-graph edge kernel (GATv2 + CGConv, dense 10x10).
// Low-smem; __launch_bounds__(256,4) caps regs at 64 -> 4 blocks/SM.
// ---------------------------------------------------------------------------
struct EdgeArgs {
    const float *xl, *xr, *fd, *fs, *sd, *ss, *xdst, *att, *b, *bf, *bs;
    float* out;
};

__global__ __launch_bounds__(256, 4) void edge_kernel(EdgeArgs A0, EdgeArgs A1)
{
    const EdgeArgs& a = blockIdx.y ? A1 : A0;
    __shared__ float s_xl[NPH*512];
    __shared__ float s_fs[NPH*128];
    __shared__ float s_ss[NPH*128];
    __shared__ float s_al[NHEADS*NPH*NPH];

    const int g = blockIdx.x, t = threadIdx.x;
    const size_t base = (size_t)g * NPH;
    const int lane = t & 31, wid = t >> 5;

    for (int v = t; v < NPH*128; v += 256) {
        int r = v >> 7, c4 = (v & 127) * 4;
        *(float4*)&s_xl[r*512 + c4] = *(const float4*)(a.xl + (base + r)*PCOLS + c4);
    }
    for (int v = t; v < NPH*32; v += 256) {
        int r = v >> 5, c4 = (v & 31) * 4;
        *(float4*)&s_fs[r*128 + c4] = *(const float4*)(a.fs + (base + r)*PCOLS + c4);
        *(float4*)&s_ss[r*128 + c4] = *(const float4*)(a.ss + (base + r)*PCOLS + c4);
    }
    __syncthreads();

#pragma unroll
    for (int pp = 0; pp < 5; pp++) {
        int p = wid + pp*8;
        int h = p / 10, j = p - h*10;
        float4 xr4 = *(const float4*)(a.xr + (base + j)*PCOLS + h*128 + lane*4);
        float4 at4 = *(const float4*)(a.att + h*128 + lane*4);
        float lg[NPH];
#pragma unroll
        for (int i = 0; i < NPH; i++) {
            float4 xl4 = *(float4*)&s_xl[i*512 + h*128 + lane*4];
            float e0 = xl4.x + xr4.x; e0 = fmaxf(e0, 0.2f*e0);
            float e1 = xl4.y + xr4.y; e1 = fmaxf(e1, 0.2f*e1);
            float e2 = xl4.z + xr4.z; e2 = fmaxf(e2, 0.2f*e2);
            float e3 = xl4.w + xr4.w; e3 = fmaxf(e3, 0.2f*e3);
            lg[i] = e0*at4.x + e1*at4.y + e2*at4.z + e3*at4.w;
        }
#pragma unroll
        for (int o = 16; o; o >>= 1)
#pragma unroll
            for (int i = 0; i < NPH; i++) lg[i] += __shfl_xor_sync(0xffffffffu, lg[i], o);
        if (lane < NPH) s_al[h*100 + j*10 + lane] = lg[lane];
    }
    __syncthreads();

    if (t < NHEADS*NPH) {
        int h = t / 10, j = t - h*10;
        float* p = s_al + h*100 + j*10;
        float m = p[0];
#pragma unroll
        for (int i = 1; i < NPH; i++) m = fmaxf(m, p[i]);
        float ex[NPH]; float sum = 0.f;
#pragma unroll
        for (int i = 0; i < NPH; i++) { ex[i] = __expf(p[i] - m); sum += ex[i]; }
        float inv = __fdividef(1.f, sum + 1e-16f);
#pragma unroll
        for (int i = 0; i < NPH; i++) p[i] = ex[i] * inv;
    }
    __syncthreads();

    for (int idx = t; idx < NPH*HD; idx += 256) {
        int j = idx >> 7, c = idx & 127;
        float gat = 0.f;
#pragma unroll
        for (int h = 0; h < NHEADS; h++) {
            const float* pal = s_al + h*100 + j*10;
            const float* pxl = s_xl + h*128 + c;
#pragma unroll
            for (int i = 0; i < NPH; i++) gat += pal[i] * pxl[i*512];
        }
        gat = 0.25f * gat + a.b[c];
        float fdv = a.fd[(base + j)*PCOLS + c] + a.bf[c];
        float sdv = a.sd[(base + j)*PCOLS + c] + a.bs[c];
        float cg = 0.f;
#pragma unroll
        for (int i = 0; i < NPH; i++) {
            float f = fdv + s_fs[i*128 + c];
            float s = sdv + s_ss[i*128 + c];
            float sig = __fdividef(1.f, 1.f + __expf(-f));
            float sp  = (s > 15.f) ? s : __logf(1.f + __expf(s));
            cg += sig * sp;
        }
        a.out[(base + j)*HD + c] = a.xdst[(base + j)*HD + c] + gat + cg;
    }
}

// ---------------------------------------------------------------------------
// Final head
// ---------------------------------------------------------------------------
__global__ __launch_bounds__(128) void final_kernel(
    const float* __restrict__ X, const float* __restrict__ W1,
    const float* __restrict__ b1, const float* __restrict__ W2,
    const float* __restrict__ b2, float* __restrict__ out)
{
    __shared__ float pool[2*HD];
    __shared__ float red[FDIM];
    const int g = blockIdx.x, t = threadIdx.x;
    const size_t base = (size_t)g * NPH;
    float pm = 0.f, po = 0.f;
#pragma unroll
    for (int r = 0; r < NPH; r++) {
        pm += X[(base + r)*HD + t];
        po += X[((size_t)NN + base + r)*HD + t];
    }
    pool[t]      = pm * 0.1f;
    pool[HD + t] = po * 0.1f;
    __syncthreads();
    float h = b1[t];
#pragma unroll 8
    for (int c = 0; c < 2*HD; c++) h += pool[c] * W1[c*FDIM + t];
    h = fminf(h, 128.f * h);
    red[t] = h * W2[t];
    __syncthreads();
    for (int s = 64; s > 0; s >>= 1) {
        if (t < s) red[t] += red[t + s];
        __syncthreads();
    }
    if (t == 0) out[g] = red[0] + b2[0];
}

// ---------------------------------------------------------------------------
// Launch
// ---------------------------------------------------------------------------
extern "C" void kernel_launch(void* const* d_in, const int* in_sizes, int n_in,
                              void* d_out, int out_size)
{
    const float* x_my  = (const float*)d_in[0];
    const float* x_opp = (const float*)d_in[1];
    const float* W_enc = (const float*)d_in[2];
    const float* b_enc = (const float*)d_in[3];
    const float* gbWl  = (const float*)d_in[4];
    const float* gbWr  = (const float*)d_in[5];
    const float* gbAtt = (const float*)d_in[6];
    const float* gbB   = (const float*)d_in[7];
    const float* grWl  = (const float*)d_in[8];
    const float* grWr  = (const float*)d_in[9];
    const float* grAtt = (const float*)d_in[10];
    const float* grB   = (const float*)d_in[11];
    const float* clWf  = (const float*)d_in[12];
    const float* clbf  = (const float*)d_in[13];
    const float* clWs  = (const float*)d_in[14];
    const float* clbs  = (const float*)d_in[15];
    const float* crWf  = (const float*)d_in[16];
    const float* crbf  = (const float*)d_in[17];
    const float* crWs  = (const float*)d_in[18];
    const float* crbs  = (const float*)d_in[19];
    const float* nodeW = (const float*)d_in[20];
    const float* nodeB = (const float*)d_in[21];
    const float* W1    = (const float*)d_in[22];
    const float* b1    = (const float*)d_in[23];
    const float* W2    = (const float*)d_in[24];
    const float* b2    = (const float*)d_in[25];
    float* out = (float*)d_out;

    float *X, *NX, *PM, *PO, *WPM, *WPO, *WN;
    cudaGetSymbolAddress((void**)&X,   g_X);
    cudaGetSymbolAddress((void**)&NX,  g_NX);
    cudaGetSymbolAddress((void**)&PM,  g_PM);
    cudaGetSymbolAddress((void**)&PO,  g_PO);
    cudaGetSymbolAddress((void**)&WPM, g_WPM);
    cudaGetSymbolAddress((void**)&WPO, g_WPO);
    cudaGetSymbolAddress((void**)&WN,  g_WN);

    cudaFuncSetAttribute(tc_gemm, cudaFuncAttributeMaxDynamicSharedMemorySize, GEMM_SMEM);

    {
        int total = NL * HD * PCOLS;
        pack_kernel<<<(total + 255)/256, 256>>>(gbWl, gbWr, grWl, grWr, clWf, clWs, crWf, crWs);
        pack_node_kernel<<<(NL*HD*HD + 255)/256, 256>>>(nodeW);
    }
    {
        int total = 2*NN*HD;
        encoder_kernel<<<(total + 255)/256, 256>>>(x_my, x_opp, W_enc, b_enc, X);
    }

    const size_t Wstep = (size_t)HD * PCOLS;
    for (int l = 0; l < NL; l++) {
        dim3 gP(PCOLS/128, NN/128, 2);
        tc_gemm<<<gP, 256, GEMM_SMEM>>>(X, X + (size_t)NN*HD,
                                        WPM + l*Wstep, WPO + l*Wstep,
                                        nullptr, PM, PO, NN, PCOLS, HD);

        EdgeArgs eo; // new_xo = GAT(beats) + CG(loses)
        eo.xl = PM + 0;    eo.xr = PO + 512;
        eo.fd = PO + 1280; eo.fs = PM + 1024;
        eo.sd = PO + 1408; eo.ss = PM + 1152;
        eo.xdst = X + (size_t)NN*HD;
        eo.att = gbAtt + l*NHEADS*HD; eo.b = gbB + l*HD;
        eo.bf = clbf + l*HD; eo.bs = clbs + l*HD;
        eo.out = NX + (size_t)NN*HD;
        EdgeArgs em; // new_xm = CG(rev_beats) + GAT(rev_loses)
        em.xl = PO + 0;    em.xr = PM + 512;
        em.fd = PM + 1280; em.fs = PO + 1024;
        em.sd = PM + 1408; em.ss = PO + 1152;
        em.xdst = X;
        em.att = grAtt + l*NHEADS*HD; em.b = grB + l*HD;
        em.bf = crbf + l*HD; em.bs = crbs + l*HD;
        em.out = NX;
        edge_kernel<<<dim3(NB, 2), 256>>>(eo, em);

        dim3 gN(HD/128, (2*NN)/128, 1);
        tc_gemm<<<gN, 256, GEMM_SMEM>>>(NX, NX, WN + l*HD*HD, WN + l*HD*HD,
                                        nodeB + l*HD, X, X, 2*NN, HD, HD);
    }

    final_kernel<<<NB, 128>>>(X, W1, b1, W2, b2, out);
}

// round 8
// speedup vs baseline: 1.0547x; 1.0547x over previous
#include <cuda_runtime.h>
#include <cuda_bf16.h>
#include <mma.h>

using namespace nvcuda;

#define NB    2048
#define NPH   10
#define NN    (NB*NPH)      // 20480
#define HD    128
#define NHEADS 4
#define NL    2
#define CDIM  32
#define FDIM  128
#define PCOLS 1536
// packed column offsets:
//   [0,512)      GAT xl
//   [512,1024)   GAT xr
//   [1024,1152)  CG fs
//   [1152,1280)  CG ss
//   [1280,1408)  CG fd
//   [1408,1536)  CG sd

// ---------------------------------------------------------------------------
// Scratch
// ---------------------------------------------------------------------------
__device__ float g_X [2*NN*HD];
__device__ float g_NX[2*NN*HD];
__device__ float g_PM[NN*PCOLS];
__device__ float g_PO[NN*PCOLS];
__device__ float g_WPM[NL*HD*PCOLS];   // tf32-rounded
__device__ float g_WPO[NL*HD*PCOLS];   // tf32-rounded
__device__ float g_WN [NL*HD*HD];      // tf32-rounded node weights

// ---------------------------------------------------------------------------
// cp.async helpers
// ---------------------------------------------------------------------------
__device__ __forceinline__ void cp_async16(void* smem_dst, const void* gmem_src) {
    unsigned saddr = (unsigned)__cvta_generic_to_shared(smem_dst);
    asm volatile("cp.async.ca.shared.global [%0], [%1], 16;\n" :: "r"(saddr), "l"(gmem_src));
}
__device__ __forceinline__ void cp_commit() {
    asm volatile("cp.async.commit_group;\n");
}
template<int N> __device__ __forceinline__ void cp_wait() {
    asm volatile("cp.async.wait_group %0;\n" :: "n"(N));
}

// ---------------------------------------------------------------------------
// Weight packing (weights pre-rounded to tf32: bit-identical to per-use RN)
// ---------------------------------------------------------------------------
__global__ void pack_kernel(const float* __restrict__ gbWl, const float* __restrict__ gbWr,
                            const float* __restrict__ grWl, const float* __restrict__ grWr,
                            const float* __restrict__ clWf, const float* __restrict__ clWs,
                            const float* __restrict__ crWf, const float* __restrict__ crWs)
{
    int idx = blockIdx.x * blockDim.x + threadIdx.x;
    const int total = NL * HD * PCOLS;
    if (idx >= total) return;
    int l   = idx / (HD * PCOLS);
    int rem = idx - l * (HD * PCOLS);
    int k   = rem / PCOLS;
    int col = rem - k * PCOLS;
    float vm, vo;
    if (col < 512) {
        vm = gbWl[(l*HD + k)*512 + col];
        vo = grWl[(l*HD + k)*512 + col];
    } else if (col < 1024) {
        int c = col - 512;
        vm = grWr[(l*HD + k)*512 + c];
        vo = gbWr[(l*HD + k)*512 + c];
    } else if (col < 1152) {
        int c = col - 1024;
        vm = clWf[(l*2*HD + HD + k)*HD + c];
        vo = crWf[(l*2*HD + HD + k)*HD + c];
    } else if (col < 1280) {
        int c = col - 1152;
        vm = clWs[(l*2*HD + HD + k)*HD + c];
        vo = crWs[(l*2*HD + HD + k)*HD + c];
    } else if (col < 1408) {
        int c = col - 1280;
        vm = crWf[(l*2*HD + k)*HD + c];
        vo = clWf[(l*2*HD + k)*HD + c];
    } else {
        int c = col - 1408;
        vm = crWs[(l*2*HD + k)*HD + c];
        vo = clWs[(l*2*HD + k)*HD + c];
    }
    g_WPM[idx] = wmma::__float_to_tf32(vm);
    g_WPO[idx] = wmma::__float_to_tf32(vo);
}

__global__ void pack_node_kernel(const float* __restrict__ nodeW)
{
    int idx = blockIdx.x * blockDim.x + threadIdx.x;
    if (idx >= NL*HD*HD) return;
    g_WN[idx] = wmma::__float_to_tf32(nodeW[idx]);
}

// ---------------------------------------------------------------------------
// Encoder
// ---------------------------------------------------------------------------
__global__ void encoder_kernel(const float* __restrict__ x_my, const float* __restrict__ x_opp,
                               const float* __restrict__ W, const float* __restrict__ b,
                               float* __restrict__ X)
{
    int idx = blockIdx.x * blockDim.x + threadIdx.x;
    if (idx >= 2*NN*HD) return;
    int row = idx >> 7, c = idx & 127;
    const float* x = (row < NN) ? (x_my + (size_t)row*CDIM) : (x_opp + (size_t)(row-NN)*CDIM);
    float acc = b[c];
#pragma unroll
    for (int k = 0; k < CDIM; k++) acc += x[k] * W[k*HD + c];
    X[idx] = acc;
}

// ---------------------------------------------------------------------------
// tf32 tensor-core GEMM (R6 config: 4 warps, warp tile 64x64, BK=32,
// cp.async double-buffered; weights pre-rounded so A converts only).
// ---------------------------------------------------------------------------
#define AS_STRIDE 36
#define BS_STRIDE 132
#define AS_STAGE  (128*AS_STRIDE)
#define BS_STAGE  (32*BS_STRIDE)
#define GEMM_SMEM ((2*AS_STAGE + 2*BS_STAGE)*4)  // 70656 B

__global__ __launch_bounds__(128) void tc_gemm(
    const float* __restrict__ A0, const float* __restrict__ A1,
    const float* __restrict__ W0, const float* __restrict__ W1,
    const float* __restrict__ bias,
    float* __restrict__ C0, float* __restrict__ C1,
    int M, int Nc, int K)
{
    const float* A = blockIdx.z ? A1 : A0;
    const float* W = blockIdx.z ? W1 : W0;
    float* C       = blockIdx.z ? C1 : C0;

    extern __shared__ float smem[];
    float* As = smem;                  // [2][128][36]
    float* Bs = smem + 2*AS_STAGE;     // [2][32][132]

    const int tid = threadIdx.x;
    const int bm = blockIdx.y * 128;
    const int bn = blockIdx.x * 128;
    const int warp = tid >> 5;
    const int wm = warp & 1;           // 64-row slab
    const int wn = warp >> 1;          // 64-col slab

    wmma::fragment<wmma::accumulator, 16, 16, 8, float> acc[4][4];

    if (bias) {
        for (int i = tid; i < 16*128; i += 128)
            As[(i >> 7)*128 + (i & 127)] = bias[bn + (i & 127)];
        __syncthreads();
#pragma unroll
        for (int mi = 0; mi < 4; mi++)
#pragma unroll
            for (int ni = 0; ni < 4; ni++)
                wmma::load_matrix_sync(acc[mi][ni], &As[wn*64 + ni*16], 128,
                                       wmma::mem_row_major);
        __syncthreads();
    } else {
#pragma unroll
        for (int mi = 0; mi < 4; mi++)
#pragma unroll
            for (int ni = 0; ni < 4; ni++)
                wmma::fill_fragment(acc[mi][ni], 0.f);
    }

    const int ar = tid >> 3, ac = (tid & 7) * 4;    // A: 16 rows/iter, 8 f4 per row
    const int br = tid >> 5, bc = (tid & 31) * 4;   // B: 4 rows/iter, 32 f4 per row

    auto load_stage = [&](int kt, int buf) {
        float* as = As + buf*AS_STAGE;
        float* bs = Bs + buf*BS_STAGE;
#pragma unroll
        for (int it = 0; it < 8; ++it) {
            int r  = ar + it*16;
            cp_async16(&as[r*AS_STRIDE + ac], A + (size_t)(bm + r)*K + kt + ac);
            int r2 = br + it*4;
            cp_async16(&bs[r2*BS_STRIDE + bc], W + (size_t)(kt + r2)*Nc + bn + bc);
        }
        cp_commit();
    };

    const int T = K >> 5;
    load_stage(0, 0);

    for (int t = 0; t < T; t++) {
        if (t + 1 < T) load_stage((t+1) << 5, (t+1) & 1);
        if (t + 1 < T) cp_wait<1>(); else cp_wait<0>();
        __syncthreads();

        const float* as = As + (t & 1)*AS_STAGE;
        const float* bs = Bs + (t & 1)*BS_STAGE;
#pragma unroll
        for (int ks = 0; ks < 32; ks += 8) {
            wmma::fragment<wmma::matrix_a, 16, 16, 8, wmma::precision::tf32,
                           wmma::row_major> a[4];
            wmma::fragment<wmma::matrix_b, 16, 16, 8, wmma::precision::tf32,
                           wmma::row_major> b[4];
#pragma unroll
            for (int mi = 0; mi < 4; mi++) {
                wmma::load_matrix_sync(a[mi], &as[(wm*64 + mi*16)*AS_STRIDE + ks], AS_STRIDE);
#pragma unroll
                for (int e = 0; e < a[mi].num_elements; e++)
                    a[mi].x[e] = wmma::__float_to_tf32(a[mi].x[e]);
            }
#pragma unroll
            for (int ni = 0; ni < 4; ni++)
                wmma::load_matrix_sync(b[ni], &bs[ks*BS_STRIDE + wn*64 + ni*16], BS_STRIDE);
#pragma unroll
            for (int mi = 0; mi < 4; mi++)
#pragma unroll
                for (int ni = 0; ni < 4; ni++)
                    wmma::mma_sync(acc[mi][ni], a[mi], b[ni], acc[mi][ni]);
        }
        __syncthreads();
    }

#pragma unroll
    for (int mi = 0; mi < 4; mi++)
#pragma unroll
        for (int ni = 0; ni < 4; ni++)
            wmma::store_matrix_sync(
                C + (size_t)(bm + wm*64 + mi*16)*Nc + bn + wn*64 + ni*16,
                acc[mi][ni], Nc, wmma::mem_row_major);
}

// ---------------------------------------------------------------------------
// Fused per-graph edge kernel (GATv2 + CGConv, dense 10x10).
// MUFU-reduced: factored exponentials (exp(-fd)·exp(-fs), exp(sd)·exp(ss))
// + FMA-pipe Newton reciprocal for the sigmoid. Only log stays on MUFU
// per (i,j,c) pair: 40 -> 12 MUFU per output element.
// ---------------------------------------------------------------------------
struct EdgeArgs {
    const float *xl, *xr, *fd, *fs, *sd, *ss, *xdst, *att, *b, *bf, *bs;
    float* out;
};

__device__ __forceinline__ float fast_rcp(float d) {
    // 1/d for d in [1, ~1e30]; seed + 3 Newton iterations (rel err < 1e-6)
    float y = __uint_as_float(0x7EF311C3u - __float_as_uint(d));
    y = y * (2.f - d*y);
    y = y * (2.f - d*y);
    y = y * (2.f - d*y);
    return y;
}

__global__ __launch_bounds__(256, 4) void edge_kernel(EdgeArgs A0, EdgeArgs A1)
{
    const EdgeArgs& a = blockIdx.y ? A1 : A0;
    __shared__ float s_xl [NPH*512];   // GAT source projections
    __shared__ float s_efs[NPH*128];   // exp(-fs_i)
    __shared__ float s_ess[NPH*128];   // exp(ss_i)
    __shared__ float s_ssr[NPH*128];   // raw ss_i (softplus guard)
    __shared__ float s_al [NHEADS*NPH*NPH];

    const int g = blockIdx.x, t = threadIdx.x;
    const size_t base = (size_t)g * NPH;
    const int lane = t & 31, wid = t >> 5;

    for (int v = t; v < NPH*128; v += 256) {
        int r = v >> 7, c4 = (v & 127) * 4;
        *(float4*)&s_xl[r*512 + c4] = *(const float4*)(a.xl + (base + r)*PCOLS + c4);
    }
    for (int v = t; v < NPH*128; v += 256) {
        int r = v >> 7, c = v & 127;
        float fsv = a.fs[(base + r)*PCOLS + c];
        float ssv = a.ss[(base + r)*PCOLS + c];
        s_efs[v] = __expf(-fsv);
        s_ess[v] = __expf(ssv);
        s_ssr[v] = ssv;
    }
    __syncthreads();

    // GAT logits: warp per (h,j)
#pragma unroll
    for (int pp = 0; pp < 5; pp++) {
        int p = wid + pp*8;
        int h = p / 10, j = p - h*10;
        float4 xr4 = *(const float4*)(a.xr + (base + j)*PCOLS + h*128 + lane*4);
        float4 at4 = *(const float4*)(a.att + h*128 + lane*4);
        float lg[NPH];
#pragma unroll
        for (int i = 0; i < NPH; i++) {
            float4 xl4 = *(float4*)&s_xl[i*512 + h*128 + lane*4];
            float e0 = xl4.x + xr4.x; e0 = fmaxf(e0, 0.2f*e0);
            float e1 = xl4.y + xr4.y; e1 = fmaxf(e1, 0.2f*e1);
            float e2 = xl4.z + xr4.z; e2 = fmaxf(e2, 0.2f*e2);
            float e3 = xl4.w + xr4.w; e3 = fmaxf(e3, 0.2f*e3);
            lg[i] = e0*at4.x + e1*at4.y + e2*at4.z + e3*at4.w;
        }
#pragma unroll
        for (int o = 16; o; o >>= 1)
#pragma unroll
            for (int i = 0; i < NPH; i++) lg[i] += __shfl_xor_sync(0xffffffffu, lg[i], o);
        if (lane < NPH) s_al[h*100 + j*10 + lane] = lg[lane];
    }
    __syncthreads();

    if (t < NHEADS*NPH) {
        int h = t / 10, j = t - h*10;
        float* p = s_al + h*100 + j*10;
        float m = p[0];
#pragma unroll
        for (int i = 1; i < NPH; i++) m = fmaxf(m, p[i]);
        float ex[NPH]; float sum = 0.f;
#pragma unroll
        for (int i = 0; i < NPH; i++) { ex[i] = __expf(p[i] - m); sum += ex[i]; }
        float inv = __fdividef(1.f, sum + 1e-16f);
#pragma unroll
        for (int i = 0; i < NPH; i++) p[i] = ex[i] * inv;
    }
    __syncthreads();

    for (int idx = t; idx < NPH*HD; idx += 256) {
        int j = idx >> 7, c = idx & 127;
        float gat = 0.f;
#pragma unroll
        for (int h = 0; h < NHEADS; h++) {
            const float* pal = s_al + h*100 + j*10;
            const float* pxl = s_xl + h*128 + c;
#pragma unroll
            for (int i = 0; i < NPH; i++) gat += pal[i] * pxl[i*512];
        }
        gat = 0.25f * gat + a.b[c];

        float fdv  = a.fd[(base + j)*PCOLS + c] + a.bf[c];
        float sdv  = a.sd[(base + j)*PCOLS + c] + a.bs[c];
        float efdn = __expf(-fdv);      // exp(-fd_j)
        float esd  = __expf(sdv);       // exp(sd_j)

        float cg = 0.f;
#pragma unroll
        for (int i = 0; i < NPH; i++) {
            float xn  = fminf(efdn * s_efs[i*128 + c], 1e30f);  // exp(-f)
            float sig = fast_rcp(1.f + xn);                      // 1/(1+e^-f)
            float s   = sdv + s_ssr[i*128 + c];
            float es  = esd * s_ess[i*128 + c];                  // exp(s)
            float sp  = (s > 15.f) ? s : __logf(1.f + es);
            cg += sig * sp;
        }
        a.out[(base + j)*HD + c] = a.xdst[(base + j)*HD + c] + gat + cg;
    }
}

// ---------------------------------------------------------------------------
// Final head
// ---------------------------------------------------------------------------
__global__ __launch_bounds__(128) void final_kernel(
    const float* __restrict__ X, const float* __restrict__ W1,
    const float* __restrict__ b1, const float* __restrict__ W2,
    const float* __restrict__ b2, float* __restrict__ out)
{
    __shared__ float pool[2*HD];
    __shared__ float red[FDIM];
    const int g = blockIdx.x, t = threadIdx.x;
    const size_t base = (size_t)g * NPH;
    float pm = 0.f, po = 0.f;
#pragma unroll
    for (int r = 0; r < NPH; r++) {
        pm += X[(base + r)*HD + t];
        po += X[((size_t)NN + base + r)*HD + t];
    }
    pool[t]      = pm * 0.1f;
    pool[HD + t] = po * 0.1f;
    __syncthreads();
    float h = b1[t];
#pragma unroll 8
    for (int c = 0; c < 2*HD; c++) h += pool[c] * W1[c*FDIM + t];
    h = fminf(h, 128.f * h);
    red[t] = h * W2[t];
    __syncthreads();
    for (int s = 64; s > 0; s >>= 1) {
        if (t < s) red[t] += red[t + s];
        __syncthreads();
    }
    if (t == 0) out[g] = red[0] + b2[0];
}

// ---------------------------------------------------------------------------
// Launch
// ---------------------------------------------------------------------------
extern "C" void kernel_launch(void* const* d_in, const int* in_sizes, int n_in,
                              void* d_out, int out_size)
{
    const float* x_my  = (const float*)d_in[0];
    const float* x_opp = (const float*)d_in[1];
    const float* W_enc = (const float*)d_in[2];
    const float* b_enc = (const float*)d_in[3];
    const float* gbWl  = (const float*)d_in[4];
    const float* gbWr  = (const float*)d_in[5];
    const float* gbAtt = (const float*)d_in[6];
    const float* gbB   = (const float*)d_in[7];
    const float* grWl  = (const float*)d_in[8];
    const float* grWr  = (const float*)d_in[9];
    const float* grAtt = (const float*)d_in[10];
    const float* grB   = (const float*)d_in[11];
    const float* clWf  = (const float*)d_in[12];
    const float* clbf  = (const float*)d_in[13];
    const float* clWs  = (const float*)d_in[14];
    const float* clbs  = (const float*)d_in[15];
    const float* crWf  = (const float*)d_in[16];
    const float* crbf  = (const float*)d_in[17];
    const float* crWs  = (const float*)d_in[18];
    const float* crbs  = (const float*)d_in[19];
    const float* nodeW = (const float*)d_in[20];
    const float* nodeB = (const float*)d_in[21];
    const float* W1    = (const float*)d_in[22];
    const float* b1    = (const float*)d_in[23];
    const float* W2    = (const float*)d_in[24];
    const float* b2    = (const float*)d_in[25];
    float* out = (float*)d_out;

    float *X, *NX, *PM, *PO, *WPM, *WPO, *WN;
    cudaGetSymbolAddress((void**)&X,   g_X);
    cudaGetSymbolAddress((void**)&NX,  g_NX);
    cudaGetSymbolAddress((void**)&PM,  g_PM);
    cudaGetSymbolAddress((void**)&PO,  g_PO);
    cudaGetSymbolAddress((void**)&WPM, g_WPM);
    cudaGetSymbolAddress((void**)&WPO, g_WPO);
    cudaGetSymbolAddress((void**)&WN,  g_WN);

    cudaFuncSetAttribute(tc_gemm, cudaFuncAttributeMaxDynamicSharedMemorySize, GEMM_SMEM);

    {
        int total = NL * HD * PCOLS;
        pack_kernel<<<(total + 255)/256, 256>>>(gbWl, gbWr, grWl, grWr, clWf, clWs, crWf, crWs);
        pack_node_kernel<<<(NL*HD*HD + 255)/256, 256>>>(nodeW);
    }
    {
        int total = 2*NN*HD;
        encoder_kernel<<<(total + 255)/256, 256>>>(x_my, x_opp, W_enc, b_enc, X);
    }

    const size_t Wstep = (size_t)HD * PCOLS;
    for (int l = 0; l < NL; l++) {
        dim3 gP(PCOLS/128, NN/128, 2);
        tc_gemm<<<gP, 128, GEMM_SMEM>>>(X, X + (size_t)NN*HD,
                                        WPM + l*Wstep, WPO + l*Wstep,
                                        nullptr, PM, PO, NN, PCOLS, HD);

        EdgeArgs eo; // new_xo = GAT(beats) + CG(loses)
        eo.xl = PM + 0;    eo.xr = PO + 512;
        eo.fd = PO + 1280; eo.fs = PM + 1024;
        eo.sd = PO + 1408; eo.ss = PM + 1152;
        eo.xdst = X + (size_t)NN*HD;
        eo.att = gbAtt + l*NHEADS*HD; eo.b = gbB + l*HD;
        eo.bf = clbf + l*HD; eo.bs = clbs + l*HD;
        eo.out = NX + (size_t)NN*HD;
        EdgeArgs em; // new_xm = CG(rev_beats) + GAT(rev_loses)
        em.xl = PO + 0;    em.xr = PM + 512;
        em.fd = PM + 1280; em.fs = PO + 1024;
        em.sd = PM + 1408; em.ss = PO + 1152;
        em.xdst = X;
        em.att = grAtt + l*NHEADS*HD; em.b = grB + l*HD;
        em.bf = crbf + l*HD; em.bs = crbs + l*HD;
        em.out = NX;
        edge_kernel<<<dim3(NB, 2), 256>>>(eo, em);

        dim3 gN(HD/128, (2*NN)/128, 1);
        tc_gemm<<<gN, 128, GEMM_SMEM>>>(NX, NX, WN + l*HD*HD, WN + l*HD*HD,
                                        nodeB + l*HD, X, X, 2*NN, HD, HD);
    }

    final_kernel<<<NB, 128>>>(X, W1, b1, W2, b2, out);
}